// round 7
// baseline (speedup 1.0000x reference)
#include <cuda_runtime.h>
#include <cuda_bf16.h>
#include <mma.h>
#include <cstdint>

using namespace nvcuda;

// Problem constants
#define BATCH   32
#define NSET    16384
#define DIM     128          // D_IN == D_OUT == 128
#define CHUNKS  128          // pass-1: 128 rows per chunk
#define ROWS_PER_CHUNK 128
#define TILE_M  128          // pass-4 rows per CTA

#define LDB     136          // padded bf16 leading dim (mult. of 8, kills LDSM conflicts)

// ---------------------------------------------------------------------------
// Device scratch (static __device__ arrays; no allocations anywhere)
// ---------------------------------------------------------------------------
__device__ float g_partial[BATCH * CHUNKS * DIM];   // 2 MB
__device__ float g_pooled[BATCH * DIM];             // 16 KB
__device__ uint4 g_w1b[2304];                       // 36864 B: w1 as bf16 [128][136]

// ---------------------------------------------------------------------------
// Pass 1: deterministic partial column-sums.  grid (CHUNKS, BATCH), 128 thr.
// Each CTA sums a 128-row x 128-col tile of x into g_partial[b][chunk][:].
// ---------------------------------------------------------------------------
__global__ void __launch_bounds__(128)
sum_kernel(const float* __restrict__ x) {
    const int b = blockIdx.y, chunk = blockIdx.x;
    const int tid = threadIdx.x, w = tid >> 5, l = tid & 31;
    const float4* xt = reinterpret_cast<const float4*>(x) +
                       (size_t)(b * NSET + chunk * ROWS_PER_CHUNK) * 32;

    float4 acc = make_float4(0.f, 0.f, 0.f, 0.f);
#pragma unroll 8
    for (int i = 0; i < 32; i++) {
        float4 v = __ldg(&xt[i * 128 + tid]);   // row = 4i + w, lane = col4
        acc.x += v.x; acc.y += v.y; acc.z += v.z; acc.w += v.w;
    }

    __shared__ float4 red[4][32];
    red[w][l] = acc;
    __syncthreads();
    if (w == 0) {
        float4 t = red[0][l];
        float4 a1 = red[1][l], a2 = red[2][l], a3 = red[3][l];
        t.x += a1.x + a2.x + a3.x;
        t.y += a1.y + a2.y + a3.y;
        t.z += a1.z + a2.z + a3.z;
        t.w += a1.w + a2.w + a3.w;
        reinterpret_cast<float4*>(&g_partial[(size_t)(b * CHUNKS + chunk) * DIM])[l] = t;
    }
}

// ---------------------------------------------------------------------------
// Pass 2: pooled[b][e] = (sum_c partial[b][c][:]) @ w2 + bias.  grid 32, 128 thr.
// ---------------------------------------------------------------------------
__global__ void __launch_bounds__(128)
pooled_kernel(const float* __restrict__ w2, const float* __restrict__ bias) {
    const int b = blockIdx.x, t = threadIdx.x;
    __shared__ float xs[DIM];
    float s = 0.f;
#pragma unroll 8
    for (int c = 0; c < CHUNKS; c++)
        s += g_partial[(size_t)(b * CHUNKS + c) * DIM + t];
    xs[t] = s;
    __syncthreads();
    float p = bias[t];
#pragma unroll 8
    for (int d = 0; d < DIM; d++)
        p += xs[d] * w2[d * DIM + t];
    g_pooled[b * DIM + t] = p;
}

// ---------------------------------------------------------------------------
// Pass 3: pre-convert w1 -> bf16 with padded leading dim LDB.  1 CTA, 128 thr.
// w1 is [K=128][N=128] row-major; stored as bf16 w1b[k*LDB + n].
// ---------------------------------------------------------------------------
__global__ void __launch_bounds__(128)
w1b_kernel(const float* __restrict__ w1) {
    const int n = threadIdx.x;
    __nv_bfloat16* dst = reinterpret_cast<__nv_bfloat16*>(g_w1b);
#pragma unroll 4
    for (int k = 0; k < DIM; k++)
        dst[k * LDB + n] = __float2bfloat16(w1[k * DIM + n]);  // coalesced over n
}

// ---------------------------------------------------------------------------
// Pass 4: out = x @ w1 (wmma bf16, HMMA) + pooled.
// grid (NSET/TILE_M, BATCH), 256 thr (8 warps), dynamic SMEM.
// SMEM: A (x tile bf16, 128 x LDB)  34816 B
//       B (w1 bf16,     128 x LDB)  36864 B (copied linearly from g_w1b)
//       P (pooled broadcast 16x128)  8192 B
// Accumulators are INITIALIZED from the pooled tile -> epilogue add is free.
// ---------------------------------------------------------------------------
#define A_BYTES 34816
#define B_BYTES 36864
#define P_BYTES 8192
#define SMEM_BYTES (A_BYTES + B_BYTES + P_BYTES)   // 79872

__global__ void __launch_bounds__(256)
ell_main(const float* __restrict__ x, float* __restrict__ out) {
    extern __shared__ char smem[];
    __nv_bfloat16* As = reinterpret_cast<__nv_bfloat16*>(smem);
    __nv_bfloat16* Bs = reinterpret_cast<__nv_bfloat16*>(smem + A_BYTES);
    float*         Ps = reinterpret_cast<float*>(smem + A_BYTES + B_BYTES);

    const int tid = threadIdx.x, wid = tid >> 5;
    const int b = blockIdx.y, nt = blockIdx.x;

    // --- B: linear 36864-byte copy of pre-converted w1 (L2-resident) ---
    {
        uint4* bd = reinterpret_cast<uint4*>(Bs);
#pragma unroll
        for (int i = 0; i < 9; i++)
            bd[i * 256 + tid] = g_w1b[i * 256 + tid];
    }

    // --- A: 128x128 fp32 -> bf16, padded row stride LDB ---
    const float4* xt = reinterpret_cast<const float4*>(x) +
                       (size_t)(b * NSET + nt * TILE_M) * 32;
#pragma unroll
    for (int i = 0; i < 16; i++) {
        int idx = i * 256 + tid;                 // 0..4095 float4s of the tile
        float4 v = __ldg(&xt[idx]);
        uint32_t h01, h23;
        asm("cvt.rn.bf16x2.f32 %0, %1, %2;" : "=r"(h01) : "f"(v.y), "f"(v.x));
        asm("cvt.rn.bf16x2.f32 %0, %1, %2;" : "=r"(h23) : "f"(v.w), "f"(v.z));
        int row = idx >> 5, col4 = idx & 31;
        uint2* dst = reinterpret_cast<uint2*>(&As[row * LDB + col4 * 4]);
        *dst = make_uint2(h01, h23);
    }

    // --- P: pooled row broadcast to 16 rows (for accumulator init) ---
    {
        const float* pr = &g_pooled[b * DIM];
#pragma unroll
        for (int i = 0; i < 8; i++) {
            int idx = i * 256 + tid;             // 0..2047
            Ps[idx] = pr[idx & 127];
        }
    }
    __syncthreads();

    // --- MMA: each warp owns a 16-row strip; 8x8 fragment grid over (k, n) ---
    const int row0 = wid * 16;
    wmma::fragment<wmma::accumulator, 16, 16, 16, float> c[8];
#pragma unroll
    for (int n = 0; n < 8; n++)
        wmma::load_matrix_sync(c[n], Ps + n * 16, 128, wmma::mem_row_major);

#pragma unroll
    for (int k = 0; k < 8; k++) {
        wmma::fragment<wmma::matrix_a, 16, 16, 16, __nv_bfloat16, wmma::row_major> a;
        wmma::load_matrix_sync(a, As + row0 * LDB + k * 16, LDB);
#pragma unroll
        for (int n = 0; n < 8; n++) {
            wmma::fragment<wmma::matrix_b, 16, 16, 16, __nv_bfloat16, wmma::row_major> bf;
            wmma::load_matrix_sync(bf, Bs + (k * 16) * LDB + n * 16, LDB);
            wmma::mma_sync(c[n], a, bf, c[n]);
        }
    }

    // --- Store: direct to global (16x16 f32 per frag; row-major ldm=128) ---
    float* obase = out + (size_t)(b * NSET + nt * TILE_M + row0) * DIM;
#pragma unroll
    for (int n = 0; n < 8; n++)
        wmma::store_matrix_sync(obase + n * 16, c[n], 128, wmma::mem_row_major);
}

// ---------------------------------------------------------------------------
// Launch
// ---------------------------------------------------------------------------
extern "C" void kernel_launch(void* const* d_in, const int* in_sizes, int n_in,
                              void* d_out, int out_size) {
    const float* x    = (const float*)d_in[0];
    const float* w1   = (const float*)d_in[1];
    const float* w2   = (const float*)d_in[2];
    const float* bias = (const float*)d_in[3];
    float* out = (float*)d_out;

    static bool attr_done = false;
    if (!attr_done) {
        cudaFuncSetAttribute(ell_main, cudaFuncAttributeMaxDynamicSharedMemorySize,
                             SMEM_BYTES);
        attr_done = true;
    }

    sum_kernel<<<dim3(CHUNKS, BATCH), 128>>>(x);
    pooled_kernel<<<BATCH, 128>>>(w2, bias);
    w1b_kernel<<<1, 128>>>(w1);
    ell_main<<<dim3(NSET / TILE_M, BATCH), 256, SMEM_BYTES>>>(x, out);
}

// round 8
// speedup vs baseline: 1.3077x; 1.3077x over previous
#include <cuda_runtime.h>
#include <cuda_bf16.h>
#include <cstdint>

// Problem constants
#define BATCH   32
#define NSET    16384
#define DIM     128
#define CHUNKS  128
#define ROWS_PER_CHUNK 128
#define TILE_M  128

#define LDE     136          // padded leading dim in elements (bf16) / floats for C
#define LDBYTES 272          // 136 * 2 bytes (bf16 rows)

// ---------------------------------------------------------------------------
// Device scratch
// ---------------------------------------------------------------------------
__device__ float g_partial[BATCH * CHUNKS * DIM];   // 2 MB
__device__ float g_pooled[BATCH * DIM];             // 16 KB
__device__ uint4 g_w1t[2176];                       // 34816 B: w1^T bf16 [n=128][k=136pad]

// ---------------------------------------------------------------------------
// Helpers
// ---------------------------------------------------------------------------
#define DI __device__ __forceinline__

DI uint32_t smem_u32(const void* p) {
    uint32_t a;
    asm("{ .reg .u64 t; cvta.to.shared.u64 t, %1; cvt.u32.u64 %0, t; }"
        : "=r"(a) : "l"(p));
    return a;
}

#define LDSM_X4(r, addr)                                                      \
    asm volatile("ldmatrix.sync.aligned.m8n8.x4.shared.b16 {%0,%1,%2,%3}, [%4];" \
                 : "=r"((r)[0]), "=r"((r)[1]), "=r"((r)[2]), "=r"((r)[3])     \
                 : "r"(addr))

#define MMA16816(c, a, b0, b1)                                                \
    asm volatile("mma.sync.aligned.m16n8k16.row.col.f32.bf16.bf16.f32 "       \
                 "{%0,%1,%2,%3}, {%4,%5,%6,%7}, {%8,%9}, {%0,%1,%2,%3};"      \
                 : "+f"((c)[0]), "+f"((c)[1]), "+f"((c)[2]), "+f"((c)[3])     \
                 : "r"((a)[0]), "r"((a)[1]), "r"((a)[2]), "r"((a)[3]),        \
                   "r"(b0), "r"(b1))

// ---------------------------------------------------------------------------
// Pass 1: deterministic partial column-sums.  grid (CHUNKS, BATCH), 128 thr.
// ---------------------------------------------------------------------------
__global__ void __launch_bounds__(128)
sum_kernel(const float* __restrict__ x) {
    const int b = blockIdx.y, chunk = blockIdx.x;
    const int tid = threadIdx.x, w = tid >> 5, l = tid & 31;
    const float4* xt = reinterpret_cast<const float4*>(x) +
                       (size_t)(b * NSET + chunk * ROWS_PER_CHUNK) * 32;

    float4 acc = make_float4(0.f, 0.f, 0.f, 0.f);
#pragma unroll 8
    for (int i = 0; i < 32; i++) {
        float4 v = __ldg(&xt[i * 128 + tid]);
        acc.x += v.x; acc.y += v.y; acc.z += v.z; acc.w += v.w;
    }

    __shared__ float4 red[4][32];
    red[w][l] = acc;
    __syncthreads();
    if (w == 0) {
        float4 t = red[0][l];
        float4 a1 = red[1][l], a2 = red[2][l], a3 = red[3][l];
        t.x += a1.x + a2.x + a3.x;
        t.y += a1.y + a2.y + a3.y;
        t.z += a1.z + a2.z + a3.z;
        t.w += a1.w + a2.w + a3.w;
        reinterpret_cast<float4*>(&g_partial[(size_t)(b * CHUNKS + chunk) * DIM])[l] = t;
    }
}

// ---------------------------------------------------------------------------
// Pass 2: pooled[b][e] = (sum_c partial[b][c][:]) @ w2 + bias.  grid 32, 128 thr.
// ---------------------------------------------------------------------------
__global__ void __launch_bounds__(128)
pooled_kernel(const float* __restrict__ w2, const float* __restrict__ bias) {
    const int b = blockIdx.x, t = threadIdx.x;
    __shared__ float xs[DIM];
    float s = 0.f;
#pragma unroll 8
    for (int c = 0; c < CHUNKS; c++)
        s += g_partial[(size_t)(b * CHUNKS + c) * DIM + t];
    xs[t] = s;
    __syncthreads();
    float p = bias[t];
#pragma unroll 8
    for (int d = 0; d < DIM; d++)
        p += xs[d] * w2[d * DIM + t];
    g_pooled[b * DIM + t] = p;
}

// ---------------------------------------------------------------------------
// Pass 3: store w1 TRANSPOSED as bf16: w1t[n][k] = w1[k][n], leading dim LDE.
// (mma "col" B operand wants n-major rows with k contiguous.)
// ---------------------------------------------------------------------------
__global__ void __launch_bounds__(128)
w1t_kernel(const float* __restrict__ w1) {
    const int k = threadIdx.x;
    __nv_bfloat16* dst = reinterpret_cast<__nv_bfloat16*>(g_w1t);
#pragma unroll 4
    for (int n = 0; n < DIM; n++)
        dst[n * LDE + k] = __float2bfloat16(w1[k * DIM + n]);  // coalesced over k
}

// ---------------------------------------------------------------------------
// Pass 4: out = x @ w1 (mma.sync bf16) + pooled.
// grid (NSET/TILE_M, BATCH), 256 thr (8 warps = 2m x 4n, warp tile 64x32).
// SMEM: A (128 x LDE bf16) 34816 | B (128 x LDE bf16) 34816 | ps 512
// C staging reuses the A+B region (128 x LDE floats = 69632 B) after MMA.
// ---------------------------------------------------------------------------
#define AB_BYTES   69632
#define SMEM_BYTES (AB_BYTES + 512)

__global__ void __launch_bounds__(256, 2)
ell_main(const float* __restrict__ x, float* __restrict__ out) {
    extern __shared__ char smem[];
    const uint32_t sb = smem_u32(smem);
    const uint32_t A0 = sb;
    const uint32_t B0 = sb + 34816u;
    float* Cs = reinterpret_cast<float*>(smem);             // staging (post-MMA)
    float* ps = reinterpret_cast<float*>(smem + AB_BYTES);  // pooled row

    const int tid = threadIdx.x, lane = tid & 31, wid = tid >> 5;
    const int b = blockIdx.y, nt = blockIdx.x;

    // --- B: linear copy of pre-transposed w1 (L2-resident, 34816 B) ---
    {
        uint4* Bs4 = reinterpret_cast<uint4*>(smem + 34816);
#pragma unroll
        for (int i = 0; i < 9; i++) {
            int idx = i * 256 + tid;
            if (idx < 2176) Bs4[idx] = g_w1t[idx];
        }
    }

    // --- A: 128x128 fp32 -> bf16, row stride LDBYTES ---
    const float4* xt = reinterpret_cast<const float4*>(x) +
                       (size_t)(b * NSET + nt * TILE_M) * 32;
#pragma unroll
    for (int i = 0; i < 16; i++) {
        int idx = i * 256 + tid;
        float4 v = __ldg(&xt[idx]);
        uint32_t h01, h23;
        asm("cvt.rn.bf16x2.f32 %0, %1, %2;" : "=r"(h01) : "f"(v.y), "f"(v.x));
        asm("cvt.rn.bf16x2.f32 %0, %1, %2;" : "=r"(h23) : "f"(v.w), "f"(v.z));
        uint32_t row = (uint32_t)idx >> 5, col4 = (uint32_t)idx & 31u;
        asm volatile("st.shared.v2.b32 [%0], {%1,%2};"
                     :: "r"(A0 + row * LDBYTES + col4 * 8u), "r"(h01), "r"(h23));
    }

    if (tid < DIM) ps[tid] = g_pooled[b * DIM + tid];
    __syncthreads();

    // --- MMA mainloop: warp (wm, wn) owns 64 rows x 32 cols ---
    const int wm = wid >> 2;   // 0..1
    const int wn = wid & 3;    // 0..3

    float c[4][4][4];          // [mf 16-row][nf 8-col][frag]
#pragma unroll
    for (int mf = 0; mf < 4; mf++)
#pragma unroll
        for (int nf = 0; nf < 4; nf++)
#pragma unroll
            for (int e = 0; e < 4; e++) c[mf][nf][e] = 0.f;

    const uint32_t lrow  = (uint32_t)(lane & 15);
    const uint32_t khalf = (uint32_t)(lane >> 4) * 16u;  // 8 elems * 2B
    uint32_t aBase[4], bBase[2];
#pragma unroll
    for (int mf = 0; mf < 4; mf++)
        aBase[mf] = A0 + (wm * 64 + mf * 16 + lrow) * LDBYTES + khalf;
#pragma unroll
    for (int p = 0; p < 2; p++)
        bBase[p] = B0 + (wn * 32 + p * 16 + lrow) * LDBYTES + khalf;

#pragma unroll
    for (int k = 0; k < 8; k++) {
        const uint32_t koff = (uint32_t)k * 32u;   // 16 elems * 2B
        uint32_t a[4][4], bb[2][4];
#pragma unroll
        for (int mf = 0; mf < 4; mf++) LDSM_X4(a[mf], aBase[mf] + koff);
#pragma unroll
        for (int p = 0; p < 2; p++)   LDSM_X4(bb[p], bBase[p] + koff);
#pragma unroll
        for (int mf = 0; mf < 4; mf++) {
#pragma unroll
            for (int nf = 0; nf < 4; nf++) {
                const int p = nf >> 1, o = nf & 1;
                MMA16816(c[mf][nf], a[mf], bb[p][o], bb[p][o + 2]);
            }
        }
    }

    __syncthreads();   // all warps done reading A/B before C staging overwrites

    // --- C staging to SMEM (stride LDE floats; conflict-free: 136 mod 32 = 8) ---
#pragma unroll
    for (int mf = 0; mf < 4; mf++) {
        const int row0 = wm * 64 + mf * 16 + (lane >> 2);
#pragma unroll
        for (int nf = 0; nf < 4; nf++) {
            const int col = wn * 32 + nf * 8 + (lane & 3) * 2;
            *reinterpret_cast<float2*>(&Cs[row0 * LDE + col]) =
                make_float2(c[mf][nf][0], c[mf][nf][1]);
            *reinterpret_cast<float2*>(&Cs[(row0 + 8) * LDE + col]) =
                make_float2(c[mf][nf][2], c[mf][nf][3]);
        }
    }
    __syncthreads();

    // --- Coalesced epilogue: row-linear float4 read + pooled add + STG.128 ---
    float4* ob = reinterpret_cast<float4*>(out + (size_t)(b * NSET + nt * TILE_M) * DIM);
    const int col4 = tid & 31;
    const float4 pv = reinterpret_cast<const float4*>(ps)[col4];
#pragma unroll
    for (int i = 0; i < 16; i++) {
        const int idx = i * 256 + tid;
        const int row = idx >> 5;
        float4 v = *reinterpret_cast<float4*>(&Cs[row * LDE + col4 * 4]);
        v.x += pv.x; v.y += pv.y; v.z += pv.z; v.w += pv.w;
        ob[idx] = v;
    }
}

// ---------------------------------------------------------------------------
// Launch
// ---------------------------------------------------------------------------
extern "C" void kernel_launch(void* const* d_in, const int* in_sizes, int n_in,
                              void* d_out, int out_size) {
    const float* x    = (const float*)d_in[0];
    const float* w1   = (const float*)d_in[1];
    const float* w2   = (const float*)d_in[2];
    const float* bias = (const float*)d_in[3];
    float* out = (float*)d_out;

    static bool attr_done = false;
    if (!attr_done) {
        cudaFuncSetAttribute(ell_main, cudaFuncAttributeMaxDynamicSharedMemorySize,
                             SMEM_BYTES);
        attr_done = true;
    }

    sum_kernel<<<dim3(CHUNKS, BATCH), 128>>>(x);
    pooled_kernel<<<BATCH, 128>>>(w2, bias);
    w1t_kernel<<<1, 128>>>(w1);
    ell_main<<<dim3(NSET / TILE_M, BATCH), 256, SMEM_BYTES>>>(x, out);
}

// round 9
// speedup vs baseline: 1.4169x; 1.0835x over previous
#include <cuda_runtime.h>
#include <cuda_bf16.h>
#include <cstdint>

// Problem constants
#define BATCH   32
#define NSET    16384
#define DIM     128
#define CHUNKS  128
#define TILE_M  128

#define LDE     136          // padded leading dim (elements)
#define LDBYTES 272          // bf16 row stride in bytes

// ---------------------------------------------------------------------------
// Device scratch (static: allowed; no runtime allocation)
// ---------------------------------------------------------------------------
__device__ float g_partial[BATCH * CHUNKS * DIM];        // 2 MB
__device__ float g_pooled[BATCH * DIM];                  // 16 KB
__device__ uint4 g_w1t[2176];                            // 34816 B: w1^T bf16 [n][k] ld=LDE
__device__ uint2 g_xbf[(size_t)BATCH * NSET * 32];       // 128 MB: x as bf16 [b][n][128]

// ---------------------------------------------------------------------------
// Helpers
// ---------------------------------------------------------------------------
#define DI __device__ __forceinline__

DI uint32_t smem_u32(const void* p) {
    uint32_t a;
    asm("{ .reg .u64 t; cvta.to.shared.u64 t, %1; cvt.u32.u64 %0, t; }"
        : "=r"(a) : "l"(p));
    return a;
}

#define LDSM_X4(r, addr)                                                      \
    asm volatile("ldmatrix.sync.aligned.m8n8.x4.shared.b16 {%0,%1,%2,%3}, [%4];" \
                 : "=r"((r)[0]), "=r"((r)[1]), "=r"((r)[2]), "=r"((r)[3])     \
                 : "r"(addr))

#define MMA16816(c, a, b0, b1)                                                \
    asm volatile("mma.sync.aligned.m16n8k16.row.col.f32.bf16.bf16.f32 "       \
                 "{%0,%1,%2,%3}, {%4,%5,%6,%7}, {%8,%9}, {%0,%1,%2,%3};"      \
                 : "+f"((c)[0]), "+f"((c)[1]), "+f"((c)[2]), "+f"((c)[3])     \
                 : "r"((a)[0]), "r"((a)[1]), "r"((a)[2]), "r"((a)[3]),        \
                   "r"(b0), "r"(b1))

// ---------------------------------------------------------------------------
// Pass 1: partial column-sums + bf16 conversion of x.
// grid (CHUNKS, BATCH), 256 thr.  Each CTA: 128x128 tile.
//   - deterministic fp32 column sums -> g_partial[b][chunk][:]
//   - x fp32 -> bf16 -> g_xbf (linear layout)
// ---------------------------------------------------------------------------
__global__ void __launch_bounds__(256)
sum_cvt_kernel(const float* __restrict__ x) {
    const int b = blockIdx.y, chunk = blockIdx.x;
    const int tid = threadIdx.x, w8 = tid >> 5, l = tid & 31;
    const size_t base = (size_t)(b * NSET + chunk * TILE_M) * 32;   // float4 units
    const float4* xt = reinterpret_cast<const float4*>(x) + base;
    uint2* xb = g_xbf + base;

    float4 acc = make_float4(0.f, 0.f, 0.f, 0.f);
#pragma unroll
    for (int i = 0; i < 16; i++) {
        const int idx = i * 256 + tid;
        float4 v = __ldg(&xt[idx]);
        acc.x += v.x; acc.y += v.y; acc.z += v.z; acc.w += v.w;
        uint32_t h01, h23;
        asm("cvt.rn.bf16x2.f32 %0, %1, %2;" : "=r"(h01) : "f"(v.y), "f"(v.x));
        asm("cvt.rn.bf16x2.f32 %0, %1, %2;" : "=r"(h23) : "f"(v.w), "f"(v.z));
        xb[idx] = make_uint2(h01, h23);
    }

    __shared__ float4 red[8][32];
    red[w8][l] = acc;
    __syncthreads();
    if (w8 == 0) {
        float4 t = red[0][l];
#pragma unroll
        for (int j = 1; j < 8; j++) {
            float4 a = red[j][l];
            t.x += a.x; t.y += a.y; t.z += a.z; t.w += a.w;
        }
        reinterpret_cast<float4*>(&g_partial[(size_t)(b * CHUNKS + chunk) * DIM])[l] = t;
    }
}

// ---------------------------------------------------------------------------
// Pass 2 (merged): blocks 0..31 -> pooled[b] = (sum partials) @ w2 + bias;
//                  block 32     -> w1^T bf16 image (ld = LDE).
// ---------------------------------------------------------------------------
__global__ void __launch_bounds__(128)
prep_kernel(const float* __restrict__ w1, const float* __restrict__ w2,
            const float* __restrict__ bias) {
    const int t = threadIdx.x;
    if (blockIdx.x == 32) {
        __nv_bfloat16* dst = reinterpret_cast<__nv_bfloat16*>(g_w1t);
#pragma unroll 4
        for (int k = 0; k < DIM; k++)
            dst[t * LDE + k] = __float2bfloat16(w1[k * DIM + t]);  // n = t
        return;
    }
    const int b = blockIdx.x;
    __shared__ float xs[DIM];
    float s = 0.f;
#pragma unroll 8
    for (int c = 0; c < CHUNKS; c++)
        s += g_partial[(size_t)(b * CHUNKS + c) * DIM + t];
    xs[t] = s;
    __syncthreads();
    float p = bias[t];
#pragma unroll 8
    for (int d = 0; d < DIM; d++)
        p += xs[d] * w2[d * DIM + t];
    g_pooled[b * DIM + t] = p;
}

// ---------------------------------------------------------------------------
// Pass 3: out = x @ w1 (mma.sync bf16) + pooled.
// grid (NSET/TILE_M, BATCH), 128 thr (4 warps = 2m x 2n, warp tile 64x64).
// SMEM: A (128 x LDE bf16) 34816 | B 34816 | ps 512; C staging reuses A+B.
// ---------------------------------------------------------------------------
#define AB_BYTES   69632
#define SMEM_BYTES (AB_BYTES + 512)

__global__ void __launch_bounds__(128, 2)
ell_main(const float* __restrict__ dummy, float* __restrict__ out) {
    extern __shared__ char smem[];
    const uint32_t sb = smem_u32(smem);
    const uint32_t A0 = sb;
    const uint32_t B0 = sb + 34816u;
    float* Cs = reinterpret_cast<float*>(smem);
    float* ps = reinterpret_cast<float*>(smem + AB_BYTES);

    const int tid = threadIdx.x, lane = tid & 31, wid = tid >> 5;
    const int b = blockIdx.y, nt = blockIdx.x;

    // --- B: linear copy of w1^T image (L2-resident, 34816 B) ---
    {
        uint4* Bs4 = reinterpret_cast<uint4*>(smem + 34816);
#pragma unroll
        for (int i = 0; i < 17; i++) {
            int idx = i * 128 + tid;
            if (idx < 2176) Bs4[idx] = g_w1t[idx];
        }
    }

    // --- A: 128x128 bf16 tile, uint4 loads, row stride LDBYTES ---
    const uint4* xb = reinterpret_cast<const uint4*>(g_xbf + (size_t)(b * NSET + nt * TILE_M) * 32);
#pragma unroll
    for (int i = 0; i < 16; i++) {
        const int idx = i * 128 + tid;              // 0..2047 uint4
        uint4 v = __ldg(&xb[idx]);
        const uint32_t row = (uint32_t)idx >> 4, col8 = (uint32_t)idx & 15u;
        asm volatile("st.shared.v4.b32 [%0], {%1,%2,%3,%4};"
                     :: "r"(A0 + row * LDBYTES + col8 * 16u),
                        "r"(v.x), "r"(v.y), "r"(v.z), "r"(v.w));
    }

    if (tid < DIM) ps[tid] = g_pooled[b * DIM + tid];
    __syncthreads();

    // --- MMA mainloop: warp (wm, wn) owns 64 rows x 64 cols ---
    const int wm = wid >> 1;   // 0..1
    const int wn = wid & 1;    // 0..1

    float c[4][8][4];          // [mf 16-row][nf 8-col][frag]
#pragma unroll
    for (int mf = 0; mf < 4; mf++)
#pragma unroll
        for (int nf = 0; nf < 8; nf++)
#pragma unroll
            for (int e = 0; e < 4; e++) c[mf][nf][e] = 0.f;

    const uint32_t lrow  = (uint32_t)(lane & 15);
    const uint32_t khalf = (uint32_t)(lane >> 4) * 16u;
    uint32_t aBase[4], bBase[4];
#pragma unroll
    for (int mf = 0; mf < 4; mf++)
        aBase[mf] = A0 + (wm * 64 + mf * 16 + lrow) * LDBYTES + khalf;
#pragma unroll
    for (int p = 0; p < 4; p++)
        bBase[p] = B0 + (wn * 64 + p * 16 + lrow) * LDBYTES + khalf;

#pragma unroll
    for (int k = 0; k < 8; k++) {
        const uint32_t koff = (uint32_t)k * 32u;
        uint32_t a[4][4], bb[4][4];
#pragma unroll
        for (int mf = 0; mf < 4; mf++) LDSM_X4(a[mf], aBase[mf] + koff);
#pragma unroll
        for (int p = 0; p < 4; p++)   LDSM_X4(bb[p], bBase[p] + koff);
#pragma unroll
        for (int mf = 0; mf < 4; mf++) {
#pragma unroll
            for (int nf = 0; nf < 8; nf++) {
                const int p = nf >> 1, o = nf & 1;
                MMA16816(c[mf][nf], a[mf], bb[p][o], bb[p][o + 2]);
            }
        }
    }

    __syncthreads();   // done reading A/B before C staging overwrites

    // --- C staging to SMEM (stride LDE; conflict-free) ---
#pragma unroll
    for (int mf = 0; mf < 4; mf++) {
        const int row0 = wm * 64 + mf * 16 + (lane >> 2);
#pragma unroll
        for (int nf = 0; nf < 8; nf++) {
            const int col = wn * 64 + nf * 8 + (lane & 3) * 2;
            *reinterpret_cast<float2*>(&Cs[row0 * LDE + col]) =
                make_float2(c[mf][nf][0], c[mf][nf][1]);
            *reinterpret_cast<float2*>(&Cs[(row0 + 8) * LDE + col]) =
                make_float2(c[mf][nf][2], c[mf][nf][3]);
        }
    }
    __syncthreads();

    // --- Coalesced epilogue: row-linear float4 + pooled add + STG.128 ---
    float4* ob = reinterpret_cast<float4*>(out + (size_t)(b * NSET + nt * TILE_M) * DIM);
    const int col4 = tid & 31;
    const float4 pv = reinterpret_cast<const float4*>(ps)[col4];
#pragma unroll
    for (int i = 0; i < 32; i++) {
        const int idx = i * 128 + tid;
        const int row = idx >> 5;
        float4 v = *reinterpret_cast<float4*>(&Cs[row * LDE + col4 * 4]);
        v.x += pv.x; v.y += pv.y; v.z += pv.z; v.w += pv.w;
        ob[idx] = v;
    }
}

// ---------------------------------------------------------------------------
// Launch
// ---------------------------------------------------------------------------
extern "C" void kernel_launch(void* const* d_in, const int* in_sizes, int n_in,
                              void* d_out, int out_size) {
    const float* x    = (const float*)d_in[0];
    const float* w1   = (const float*)d_in[1];
    const float* w2   = (const float*)d_in[2];
    const float* bias = (const float*)d_in[3];
    float* out = (float*)d_out;

    static bool attr_done = false;
    if (!attr_done) {
        cudaFuncSetAttribute(ell_main, cudaFuncAttributeMaxDynamicSharedMemorySize,
                             SMEM_BYTES);
        attr_done = true;
    }

    sum_cvt_kernel<<<dim3(CHUNKS, BATCH), 256>>>(x);
    prep_kernel<<<33, 128>>>(w1, w2, bias);
    ell_main<<<dim3(NSET / TILE_M, BATCH), 128, SMEM_BYTES>>>(x, out);
}